// round 17
// baseline (speedup 1.0000x reference)
#include <cuda_runtime.h>
#include <cuda_bf16.h>

// HGNN forward, single kernel. Grid (256 graphs x 2 e-halves), 256 threads.
//   Per block: 24 hyperedges of one graph.
//   M[e,d]  = (1/32) * sum_v H[v,e]*x[v,d]
//   ED[e,f] = relu(sum_d M[e,d]*W[f,d] + b[f])  -> h_e
//   partial c -> Cscratch (stcg); last half-block per graph via
//   atom.add.acq_rel.gpu counter sums both partials in fixed order.
// Output buffer: [ c (B*D) | h_e (B*E*D) ]
//
// R17: R13's cheap tiles + enough block-level parallelism to overlap the
// serial phase chain: 512 blocks -> 3.46 blocks/SM (R13 had 1.73, R15 had 1
// fat block; both latency-starved at issue~30%). W staged 2x per graph
// (vs R8's 4x). FFMA2 retained.

constexpr int V   = 8192;
constexpr int E   = 48;
constexpr int D   = 64;
constexpr int B   = 256;
constexpr int NPG = V / B;     // 32 nodes per graph
constexpr int EQN = 2;         // e-halves
constexpr int EPB = E / EQN;   // 24 edges per block
constexpr int NT  = 256;
constexpr int WS  = 68;        // W shared row stride (floats)

typedef unsigned long long ull;

__device__ __forceinline__ void ffma2(ull& acc, ull a, ull b) {
    asm("fma.rn.f32x2 %0, %1, %2, %0;" : "+l"(acc) : "l"(a), "l"(b));
}
__device__ __forceinline__ ull pack2(float lo, float hi) {
    ull r;
    asm("mov.b64 %0, {%1, %2};" : "=l"(r) : "f"(lo), "f"(hi));
    return r;
}
__device__ __forceinline__ float sum2(ull v) {
    float lo, hi;
    asm("mov.b64 {%0, %1}, %2;" : "=f"(lo), "=f"(hi) : "l"(v));
    return lo + hi;
}

__device__ float Cscratch[EQN * B * D];   // partial-c scratch (L2 via stcg)
__device__ int   Ctr[B];                  // arrival counters (zero-init; reset by last block)

__global__ __launch_bounds__(NT, 3) void hgnn_kernel(
    const float* __restrict__ x,     // (V, D)
    const float* __restrict__ Hm,    // (V, E)
    const float* __restrict__ W,     // (D, D) row-major [f][d]
    const float* __restrict__ bias,  // (D,)
    float* __restrict__ out)         // [c | h_e]
{
    __shared__ float Ht[EPB * NPG];   // 3 KB   Ht[e*32+v]
    __shared__ float Ws[D * WS];      // 17 KB  Ws[f*68+d]
    __shared__ float Ms[EPB * D];     // 6 KB
    __shared__ float Sv[EPB];
    __shared__ float Bs[D];
    __shared__ float Cp[8][D];        // 2 KB
    __shared__ int   isLast;

    const int b  = blockIdx.x;
    const int eq = blockIdx.y;
    const int t  = threadIdx.x;

    // ---- stage H slice transposed: Ht[e*32+v] = H[v, eq*24+e] ----
    {
        const float* hb = Hm + (size_t)b * NPG * E + eq * EPB;
        if (t < NPG * 6) {                        // 192 float4 loads
            int v = t / 6, g = t - (t / 6) * 6;
            float4 h = *(const float4*)(hb + v * E + g * 4);
            int e = g * 4;
            Ht[(e + 0) * NPG + v] = h.x;
            Ht[(e + 1) * NPG + v] = h.y;
            Ht[(e + 2) * NPG + v] = h.z;
            Ht[(e + 3) * NPG + v] = h.w;
        }
        // ---- stage W rows into Ws[f*68 + d] (coalesced LDG.128) ----
        #pragma unroll
        for (int i = t; i < D * D / 4; i += NT) {
            float4 w = ((const float4*)W)[i];
            int fw = i >> 4, d4 = (i & 15) * 4;
            *(float4*)&Ws[fw * WS + d4] = w;
        }
        if (t < D) Bs[t] = bias[t];
    }
    __syncthreads();

    // ---- s[e] = sum_v Ht[e,v] ----
    if (t < EPB) {
        const float4* hr = (const float4*)&Ht[t * NPG];
        float a0 = 0.f, a1 = 0.f;
        #pragma unroll
        for (int k = 0; k < NPG / 8; k++) {
            float4 h0 = hr[2 * k], h1 = hr[2 * k + 1];
            a0 += h0.x + h0.y + h0.z + h0.w;
            a1 += h1.x + h1.y + h1.z + h1.w;
        }
        Sv[t] = a0 + a1;
    }

    // ---- phase 1: M[e,f]; f = t&63, qq = t>>6, e = j*4+qq, j=0..5 ----
    {
        const int f = t & 63, qq = t >> 6;
        ull macc2[6] = {0, 0, 0, 0, 0, 0};

        #pragma unroll
        for (int vc = 0; vc < 2; vc++) {
            float xr[16];
            const float* xg = x + (size_t)b * NPG * D + (vc * 16) * D + f;
            #pragma unroll
            for (int v = 0; v < 16; v++) xr[v] = xg[v * D];   // coalesced

            ull xp[8];
            #pragma unroll
            for (int k = 0; k < 8; k++) xp[k] = pack2(xr[2 * k], xr[2 * k + 1]);

            #pragma unroll
            for (int j = 0; j < 6; j++) {
                int e = j * 4 + qq;
                const ulonglong2* hr = (const ulonglong2*)&Ht[e * NPG + vc * 16];
                #pragma unroll
                for (int k = 0; k < 4; k++) {
                    ulonglong2 h = hr[k];
                    ffma2(macc2[j], h.x, xp[2 * k + 0]);
                    ffma2(macc2[j], h.y, xp[2 * k + 1]);
                }
            }
        }
        #pragma unroll
        for (int j = 0; j < 6; j++)
            Ms[(j * 4 + qq) * D + f] = sum2(macc2[j]) * (1.0f / NPG);
    }
    __syncthreads();

    // ---- phase 2: tile (3e x 2f); u = t&31, es = t>>5; e = j*8+es ----
    {
        const int u = t & 31, es = t >> 5;
        ull acc2a[3] = {0, 0, 0};
        ull acc2b[3] = {0, 0, 0};

        #pragma unroll
        for (int dc = 0; dc < 4; dc++) {
            ulonglong2 wa[4], wb[4];
            const ulonglong2* wra = (const ulonglong2*)&Ws[u * WS + dc * 16];
            const ulonglong2* wrb = (const ulonglong2*)&Ws[(u + 32) * WS + dc * 16];
            #pragma unroll
            for (int k = 0; k < 4; k++) { wa[k] = wra[k]; wb[k] = wrb[k]; }

            #pragma unroll
            for (int j = 0; j < 3; j++) {
                int e = j * 8 + es;
                const ulonglong2* mr = (const ulonglong2*)&Ms[e * D + dc * 16]; // bcast
                #pragma unroll
                for (int k = 0; k < 4; k++) {
                    ulonglong2 m = mr[k];
                    ffma2(acc2a[j], m.x, wa[k].x);
                    ffma2(acc2a[j], m.y, wa[k].y);
                    ffma2(acc2b[j], m.x, wb[k].x);
                    ffma2(acc2b[j], m.y, wb[k].y);
                }
            }
        }

        // relu, h_e store, c fold
        float c0 = 0.f, c1 = 0.f;
        float* he = out + (size_t)B * D + ((size_t)b * E + eq * EPB) * D;
        const float bf0 = Bs[u], bf1 = Bs[u + 32];
        #pragma unroll
        for (int j = 0; j < 3; j++) {
            int e = j * 8 + es;
            float r0 = fmaxf(sum2(acc2a[j]) + bf0, 0.f);
            float r1 = fmaxf(sum2(acc2b[j]) + bf1, 0.f);
            he[e * D + u]      = r0;     // coalesced
            he[e * D + u + 32] = r1;     // coalesced
            float sv = Sv[e];
            c0 = fmaf(sv, r0, c0);
            c1 = fmaf(sv, r1, c1);
        }
        Cp[es][u]      = c0;
        Cp[es][u + 32] = c1;
    }
    __syncthreads();

    // ---- partial c -> L2 scratch; last half-block per graph reduces ----
    if (t < D) {
        float c = 0.f;
        #pragma unroll
        for (int k = 0; k < 8; k++) c += Cp[k][t];
        __stcg(&Cscratch[(eq * B + b) * D + t], c);
    }
    __syncthreads();   // all partial stores happen-before t0's release

    if (t == 0) {
        int old;
        asm volatile("atom.add.acq_rel.gpu.global.s32 %0, [%1], 1;"
                     : "=r"(old) : "l"(&Ctr[b]) : "memory");
        isLast = (old == EQN - 1);
    }
    __syncthreads();   // t0's acquire happens-before consumer loads

    if (isLast) {
        if (t < D) {
            float s = __ldcg(&Cscratch[b * D + t])
                    + __ldcg(&Cscratch[(B + b) * D + t]);
            out[b * D + t] = s * (1.0f / (NPG * E));
        }
        if (t == 0) Ctr[b] = 0;          // clean for next replay
    }
}

extern "C" void kernel_launch(void* const* d_in, const int* in_sizes, int n_in,
                              void* d_out, int out_size) {
    const float* x    = (const float*)d_in[0];   // (V,D)
    const float* Hm   = (const float*)d_in[1];   // (V,E)
    const float* W    = (const float*)d_in[2];   // (D,D)
    const float* bias = (const float*)d_in[3];   // (D,)
    float* out = (float*)d_out;

    dim3 grid(B, EQN);
    hgnn_kernel<<<grid, NT>>>(x, Hm, W, bias, out);
}